// round 11
// baseline (speedup 1.0000x reference)
#include <cuda_runtime.h>
#include <math.h>

// Problem constants (fixed by the reference setup_inputs)
#define NN 100000          // nodes
#define NE 3200000         // edges
#define NC 16              // classes

#define LBLOCKS 1024
#define LTHREADS 256

// ---- scratch (device globals; no allocations allowed) ----
__device__ __align__(16) float g_sums[NN * NC];   // scatter sums
__device__ float  g_cnt[NN];                      // in-degree (as float)
__device__ __align__(16) float g_ls[NN * NC];     // log(avg + 1e-10)
__device__ __align__(16) float g_d[NN * NC];      // sharp + 1e-10
__device__ float  g_dlogd[NN];                    // sum_c d*log(d)
__device__ float  g_partials[LBLOCKS];            // per-block loss partials

// Vectorized fp32 reduction to global memory (PTX ISA 8.1+, sm_90+).
// One L2 reduction op for 4 floats instead of 4 scalar REDs.
__device__ __forceinline__ void red_add_v4(float* addr, float a, float b,
                                           float c, float d) {
    asm volatile("red.global.add.v4.f32 [%0], {%1, %2, %3, %4};"
                 :: "l"(__cvta_generic_to_global(addr)),
                    "f"(a), "f"(b), "f"(c), "f"(d)
                 : "memory");
}

// ---------------------------------------------------------------------------
// K0: zero the accumulators (graph-replay safe: re-zeroed every launch)
// ---------------------------------------------------------------------------
__global__ void k_init() {
    int i = blockIdx.x * blockDim.x + threadIdx.x;
    int stride = gridDim.x * blockDim.x;
    float4 z = make_float4(0.f, 0.f, 0.f, 0.f);
    float4* s4 = reinterpret_cast<float4*>(g_sums);
    for (int j = i; j < (NN * NC) / 4; j += stride) s4[j] = z;
    for (int j = i; j < NN; j += stride) g_cnt[j] = 0.f;
}

// ---------------------------------------------------------------------------
// K1: scatter-add  sums[dst] += aug_pred[src],  cnt[dst] += 1
// One thread per edge; 4 x red.v4 + 1 scalar red.
// ---------------------------------------------------------------------------
__global__ void k_scatter(const int* __restrict__ src,
                          const int* __restrict__ dst,
                          const float4* __restrict__ aug4) {
    int e = blockIdx.x * blockDim.x + threadIdx.x;
    if (e >= NE) return;
    int s = src[e];
    int t = dst[e];
    float4 a0 = aug4[s * 4 + 0];
    float4 a1 = aug4[s * 4 + 1];
    float4 a2 = aug4[s * 4 + 2];
    float4 a3 = aug4[s * 4 + 3];
    float* base = g_sums + t * NC;
    red_add_v4(base +  0, a0.x, a0.y, a0.z, a0.w);
    red_add_v4(base +  4, a1.x, a1.y, a1.z, a1.w);
    red_add_v4(base +  8, a2.x, a2.y, a2.z, a2.w);
    red_add_v4(base + 12, a3.x, a3.y, a3.z, a3.w);
    atomicAdd(&g_cnt[t], 1.0f);
}

// ---------------------------------------------------------------------------
// K2: per-node epilogue
//   avg = sums / max(cnt,1);  p = avg^2 (TEMP=0.5);  sharp = p / sum(p)
//   ls = log(avg + 1e-10);  d = sharp + 1e-10;  dlogd = sum_c d*log(d)
// ---------------------------------------------------------------------------
__global__ void k_node() {
    int i = blockIdx.x * blockDim.x + threadIdx.x;
    if (i >= NN) return;

    float inv = 1.0f / fmaxf(g_cnt[i], 1.0f);
    const float4* s4 = reinterpret_cast<const float4*>(g_sums) + i * 4;

    float avg[NC];
#pragma unroll
    for (int k = 0; k < 4; k++) {
        float4 v = s4[k];
        avg[4 * k + 0] = v.x * inv;
        avg[4 * k + 1] = v.y * inv;
        avg[4 * k + 2] = v.z * inv;
        avg[4 * k + 3] = v.w * inv;
    }

    float p[NC];
    float psum = 0.f;
#pragma unroll
    for (int c = 0; c < NC; c++) { p[c] = avg[c] * avg[c]; psum += p[c]; }
    float invp = 1.0f / psum;

    float dv[NC], lsv[NC];
    float dlogd = 0.f;
#pragma unroll
    for (int c = 0; c < NC; c++) {
        float d = p[c] * invp + 1e-10f;
        dv[c]  = d;
        dlogd += d * logf(d);
        lsv[c] = logf(avg[c] + 1e-10f);
    }

    float4* d4  = reinterpret_cast<float4*>(g_d)  + i * 4;
    float4* ls4 = reinterpret_cast<float4*>(g_ls) + i * 4;
#pragma unroll
    for (int k = 0; k < 4; k++) {
        d4[k]  = make_float4(dv[4*k], dv[4*k+1], dv[4*k+2], dv[4*k+3]);
        ls4[k] = make_float4(lsv[4*k], lsv[4*k+1], lsv[4*k+2], lsv[4*k+3]);
    }
    g_dlogd[i] = dlogd;
}

// ---------------------------------------------------------------------------
// K3: edge loss  loss_e = dlogd[dst] - dot(d[dst], ls[src])
// Pure gather; per-block float partials (no global atomic hotspot).
// ---------------------------------------------------------------------------
__global__ void k_loss(const int* __restrict__ src,
                       const int* __restrict__ dst) {
    int tid = blockIdx.x * blockDim.x + threadIdx.x;
    int stride = gridDim.x * blockDim.x;
    const float4* ls4 = reinterpret_cast<const float4*>(g_ls);
    const float4* d4  = reinterpret_cast<const float4*>(g_d);

    float local = 0.f;
    for (int e = tid; e < NE; e += stride) {
        int s = src[e];
        int t = dst[e];
        float4 l0 = ls4[s * 4 + 0], l1 = ls4[s * 4 + 1];
        float4 l2 = ls4[s * 4 + 2], l3 = ls4[s * 4 + 3];
        float4 d0 = d4[t * 4 + 0],  d1 = d4[t * 4 + 1];
        float4 d2 = d4[t * 4 + 2],  d3 = d4[t * 4 + 3];
        float dot = 0.f;
        dot = fmaf(d0.x, l0.x, dot); dot = fmaf(d0.y, l0.y, dot);
        dot = fmaf(d0.z, l0.z, dot); dot = fmaf(d0.w, l0.w, dot);
        dot = fmaf(d1.x, l1.x, dot); dot = fmaf(d1.y, l1.y, dot);
        dot = fmaf(d1.z, l1.z, dot); dot = fmaf(d1.w, l1.w, dot);
        dot = fmaf(d2.x, l2.x, dot); dot = fmaf(d2.y, l2.y, dot);
        dot = fmaf(d2.z, l2.z, dot); dot = fmaf(d2.w, l2.w, dot);
        dot = fmaf(d3.x, l3.x, dot); dot = fmaf(d3.y, l3.y, dot);
        dot = fmaf(d3.z, l3.z, dot); dot = fmaf(d3.w, l3.w, dot);
        local += g_dlogd[t] - dot;
    }

    // block reduce (float)
    __shared__ float sm[LTHREADS / 32];
#pragma unroll
    for (int o = 16; o > 0; o >>= 1)
        local += __shfl_xor_sync(0xffffffffu, local, o);
    if ((threadIdx.x & 31) == 0) sm[threadIdx.x >> 5] = local;
    __syncthreads();
    if (threadIdx.x < (LTHREADS / 32)) {
        float v = sm[threadIdx.x];
#pragma unroll
        for (int o = (LTHREADS / 64); o > 0; o >>= 1)
            v += __shfl_xor_sync(0x000000ffu, v, o);
        if (threadIdx.x == 0) g_partials[blockIdx.x] = v;
    }
}

// ---------------------------------------------------------------------------
// K4: final reduction of block partials (double), write scalar mean
// ---------------------------------------------------------------------------
__global__ void k_final(float* __restrict__ out) {
    __shared__ double sm[8];
    double v = 0.0;
    for (int j = threadIdx.x; j < LBLOCKS; j += blockDim.x)
        v += (double)g_partials[j];
#pragma unroll
    for (int o = 16; o > 0; o >>= 1)
        v += __shfl_xor_sync(0xffffffffu, v, o);
    if ((threadIdx.x & 31) == 0) sm[threadIdx.x >> 5] = v;
    __syncthreads();
    if (threadIdx.x == 0) {
        double t = 0.0;
#pragma unroll
        for (int k = 0; k < 8; k++) t += sm[k];
        out[0] = (float)(t / (double)NE);
    }
}

// ---------------------------------------------------------------------------
extern "C" void kernel_launch(void* const* d_in, const int* in_sizes, int n_in,
                              void* d_out, int out_size) {
    const int* edge = (const int*)d_in[0];          // [2, E] int32
    const int* src  = edge;                         // edge_index[0]
    const int* dst  = edge + NE;                    // edge_index[1]
    const float4* aug4 = (const float4*)d_in[1];    // [N, 16] fp32, 64B rows
    float* out = (float*)d_out;

    k_init<<<512, 256>>>();
    k_scatter<<<(NE + 255) / 256, 256>>>(src, dst, aug4);
    k_node<<<(NN + 255) / 256, 256>>>();
    k_loss<<<LBLOCKS, LTHREADS>>>(src, dst);
    k_final<<<1, 256>>>(out);
}

// round 12
// speedup vs baseline: 1.0006x; 1.0006x over previous
#include <cuda_runtime.h>
#include <math.h>

// Problem constants (fixed by the reference setup_inputs)
#define NN 100000          // nodes
#define NE 3200000         // edges
#define NC 16              // classes

#define LBLOCKS 1024
#define LTHREADS 256

// ---- scratch (device globals; no allocations allowed) ----
__device__ __align__(16) float g_sums[NN * NC];   // scatter sums
__device__ float  g_cnt[NN];                      // in-degree (as float)
__device__ __align__(16) float g_ls[NN * NC];     // log(avg + 1e-10)
__device__ __align__(16) float g_d[NN * NC];      // sharp + 1e-10
__device__ float  g_dlogd[NN];                    // sum_c d*log(d)
__device__ float  g_partials[LBLOCKS];            // per-block loss partials

// Vectorized fp32 reduction to global memory (PTX ISA 8.1+, sm_90+).
// One L2 reduction op for 4 floats instead of 4 scalar REDs.
__device__ __forceinline__ void red_add_v4(float* addr, float a, float b,
                                           float c, float d) {
    asm volatile("red.global.add.v4.f32 [%0], {%1, %2, %3, %4};"
                 :: "l"(__cvta_generic_to_global(addr)),
                    "f"(a), "f"(b), "f"(c), "f"(d)
                 : "memory");
}

// ---------------------------------------------------------------------------
// K0: zero the accumulators (graph-replay safe: re-zeroed every launch)
// ---------------------------------------------------------------------------
__global__ void k_init() {
    int i = blockIdx.x * blockDim.x + threadIdx.x;
    int stride = gridDim.x * blockDim.x;
    float4 z = make_float4(0.f, 0.f, 0.f, 0.f);
    float4* s4 = reinterpret_cast<float4*>(g_sums);
    for (int j = i; j < (NN * NC) / 4; j += stride) s4[j] = z;
    for (int j = i; j < NN; j += stride) g_cnt[j] = 0.f;
}

// ---------------------------------------------------------------------------
// K1: scatter-add  sums[dst] += aug_pred[src],  cnt[dst] += 1
// One thread per edge; 4 x red.v4 + 1 scalar red.
// ---------------------------------------------------------------------------
__global__ void k_scatter(const int* __restrict__ src,
                          const int* __restrict__ dst,
                          const float4* __restrict__ aug4) {
    int e = blockIdx.x * blockDim.x + threadIdx.x;
    if (e >= NE) return;
    int s = src[e];
    int t = dst[e];
    float4 a0 = aug4[s * 4 + 0];
    float4 a1 = aug4[s * 4 + 1];
    float4 a2 = aug4[s * 4 + 2];
    float4 a3 = aug4[s * 4 + 3];
    float* base = g_sums + t * NC;
    red_add_v4(base +  0, a0.x, a0.y, a0.z, a0.w);
    red_add_v4(base +  4, a1.x, a1.y, a1.z, a1.w);
    red_add_v4(base +  8, a2.x, a2.y, a2.z, a2.w);
    red_add_v4(base + 12, a3.x, a3.y, a3.z, a3.w);
    atomicAdd(&g_cnt[t], 1.0f);
}

// ---------------------------------------------------------------------------
// K2: per-node epilogue
//   avg = sums / max(cnt,1);  p = avg^2 (TEMP=0.5);  sharp = p / sum(p)
//   ls = log(avg + 1e-10);  d = sharp + 1e-10;  dlogd = sum_c d*log(d)
// ---------------------------------------------------------------------------
__global__ void k_node() {
    int i = blockIdx.x * blockDim.x + threadIdx.x;
    if (i >= NN) return;

    float inv = 1.0f / fmaxf(g_cnt[i], 1.0f);
    const float4* s4 = reinterpret_cast<const float4*>(g_sums) + i * 4;

    float avg[NC];
#pragma unroll
    for (int k = 0; k < 4; k++) {
        float4 v = s4[k];
        avg[4 * k + 0] = v.x * inv;
        avg[4 * k + 1] = v.y * inv;
        avg[4 * k + 2] = v.z * inv;
        avg[4 * k + 3] = v.w * inv;
    }

    float p[NC];
    float psum = 0.f;
#pragma unroll
    for (int c = 0; c < NC; c++) { p[c] = avg[c] * avg[c]; psum += p[c]; }
    float invp = 1.0f / psum;

    float dv[NC], lsv[NC];
    float dlogd = 0.f;
#pragma unroll
    for (int c = 0; c < NC; c++) {
        float d = p[c] * invp + 1e-10f;
        dv[c]  = d;
        dlogd += d * logf(d);
        lsv[c] = logf(avg[c] + 1e-10f);
    }

    float4* d4  = reinterpret_cast<float4*>(g_d)  + i * 4;
    float4* ls4 = reinterpret_cast<float4*>(g_ls) + i * 4;
#pragma unroll
    for (int k = 0; k < 4; k++) {
        d4[k]  = make_float4(dv[4*k], dv[4*k+1], dv[4*k+2], dv[4*k+3]);
        ls4[k] = make_float4(lsv[4*k], lsv[4*k+1], lsv[4*k+2], lsv[4*k+3]);
    }
    g_dlogd[i] = dlogd;
}

// ---------------------------------------------------------------------------
// K3: edge loss  loss_e = dlogd[dst] - dot(d[dst], ls[src])
// Pure gather; per-block float partials (no global atomic hotspot).
// ---------------------------------------------------------------------------
__global__ void k_loss(const int* __restrict__ src,
                       const int* __restrict__ dst) {
    int tid = blockIdx.x * blockDim.x + threadIdx.x;
    int stride = gridDim.x * blockDim.x;
    const float4* ls4 = reinterpret_cast<const float4*>(g_ls);
    const float4* d4  = reinterpret_cast<const float4*>(g_d);

    float local = 0.f;
    for (int e = tid; e < NE; e += stride) {
        int s = src[e];
        int t = dst[e];
        float4 l0 = ls4[s * 4 + 0], l1 = ls4[s * 4 + 1];
        float4 l2 = ls4[s * 4 + 2], l3 = ls4[s * 4 + 3];
        float4 d0 = d4[t * 4 + 0],  d1 = d4[t * 4 + 1];
        float4 d2 = d4[t * 4 + 2],  d3 = d4[t * 4 + 3];
        float dot = 0.f;
        dot = fmaf(d0.x, l0.x, dot); dot = fmaf(d0.y, l0.y, dot);
        dot = fmaf(d0.z, l0.z, dot); dot = fmaf(d0.w, l0.w, dot);
        dot = fmaf(d1.x, l1.x, dot); dot = fmaf(d1.y, l1.y, dot);
        dot = fmaf(d1.z, l1.z, dot); dot = fmaf(d1.w, l1.w, dot);
        dot = fmaf(d2.x, l2.x, dot); dot = fmaf(d2.y, l2.y, dot);
        dot = fmaf(d2.z, l2.z, dot); dot = fmaf(d2.w, l2.w, dot);
        dot = fmaf(d3.x, l3.x, dot); dot = fmaf(d3.y, l3.y, dot);
        dot = fmaf(d3.z, l3.z, dot); dot = fmaf(d3.w, l3.w, dot);
        local += g_dlogd[t] - dot;
    }

    // block reduce (float)
    __shared__ float sm[LTHREADS / 32];
#pragma unroll
    for (int o = 16; o > 0; o >>= 1)
        local += __shfl_xor_sync(0xffffffffu, local, o);
    if ((threadIdx.x & 31) == 0) sm[threadIdx.x >> 5] = local;
    __syncthreads();
    if (threadIdx.x < (LTHREADS / 32)) {
        float v = sm[threadIdx.x];
#pragma unroll
        for (int o = (LTHREADS / 64); o > 0; o >>= 1)
            v += __shfl_xor_sync(0x000000ffu, v, o);
        if (threadIdx.x == 0) g_partials[blockIdx.x] = v;
    }
}

// ---------------------------------------------------------------------------
// K4: final reduction of block partials (double), write scalar mean
// ---------------------------------------------------------------------------
__global__ void k_final(float* __restrict__ out) {
    __shared__ double sm[8];
    double v = 0.0;
    for (int j = threadIdx.x; j < LBLOCKS; j += blockDim.x)
        v += (double)g_partials[j];
#pragma unroll
    for (int o = 16; o > 0; o >>= 1)
        v += __shfl_xor_sync(0xffffffffu, v, o);
    if ((threadIdx.x & 31) == 0) sm[threadIdx.x >> 5] = v;
    __syncthreads();
    if (threadIdx.x == 0) {
        double t = 0.0;
#pragma unroll
        for (int k = 0; k < 8; k++) t += sm[k];
        out[0] = (float)(t / (double)NE);
    }
}

// ---------------------------------------------------------------------------
extern "C" void kernel_launch(void* const* d_in, const int* in_sizes, int n_in,
                              void* d_out, int out_size) {
    const int* edge = (const int*)d_in[0];          // [2, E] int32
    const int* src  = edge;                         // edge_index[0]
    const int* dst  = edge + NE;                    // edge_index[1]
    const float4* aug4 = (const float4*)d_in[1];    // [N, 16] fp32, 64B rows
    float* out = (float*)d_out;

    k_init<<<512, 256>>>();
    k_scatter<<<(NE + 255) / 256, 256>>>(src, dst, aug4);
    k_node<<<(NN + 255) / 256, 256>>>();
    k_loss<<<LBLOCKS, LTHREADS>>>(src, dst);
    k_final<<<1, 256>>>(out);
}